// round 15
// baseline (speedup 1.0000x reference)
#include <cuda_runtime.h>
#include <cuda_fp16.h>
#include <cstddef>
#include <cstdint>

#define B_   8
#define T_   1024
#define C_   1024
#define H_   16
#define HD_  64
#define BH_  (B_ * H_)          // 128
#define C3_  (3 * C_)           // 3072
#define KW_  1024               // K for all GEMMs (hi-only)
#define TH_  0.001f
#define PQ_  72                 // staging pitch (halves) for 64-wide tiles
#define PS_  1032               // S panel pitch (halves): 2064 B rows

using ushort_t = unsigned short;

// ---------------- scratch (static device globals) ----------------
__device__ __align__(16) ushort_t g_qkvh[(size_t)B_ * T_ * C3_];        // fp16 hi QKV
__device__ __align__(16) ushort_t g_yh[(size_t)B_ * T_ * C_];           // fp16 hi Y
__device__ __align__(16) ushort_t g_xh[(size_t)B_ * T_ * C_];           // fp16 hi x
__device__ __align__(16) ushort_t g_wa[(size_t)C3_ * KW_];              // w_attn^T hi
__device__ __align__(16) ushort_t g_wp[(size_t)C_ * KW_];               // w_proj^T hi

// ---------------- helpers ----------------
__device__ __forceinline__ uint32_t smem_u32(const void* p) {
    uint32_t a;
    asm("{ .reg .u64 t; cvta.to.shared.u64 t, %1; cvt.u32.u64 %0, t; }"
        : "=r"(a) : "l"(p));
    return a;
}
__device__ __forceinline__ void ldsm4(uint32_t (&r)[4], uint32_t addr) {
    asm volatile("ldmatrix.sync.aligned.m8n8.x4.shared.b16 {%0,%1,%2,%3}, [%4];"
        : "=r"(r[0]), "=r"(r[1]), "=r"(r[2]), "=r"(r[3]) : "r"(addr));
}
__device__ __forceinline__ void ldsm4t(uint32_t (&r)[4], uint32_t addr) {
    asm volatile("ldmatrix.sync.aligned.m8n8.x4.trans.shared.b16 {%0,%1,%2,%3}, [%4];"
        : "=r"(r[0]), "=r"(r[1]), "=r"(r[2]), "=r"(r[3]) : "r"(addr));
}
__device__ __forceinline__ void mma16816(float (&d)[4], const uint32_t (&a)[4],
                                         uint32_t b0, uint32_t b1) {
    asm volatile(
        "mma.sync.aligned.m16n8k16.row.col.f32.f16.f16.f32 "
        "{%0,%1,%2,%3}, {%4,%5,%6,%7}, {%8,%9}, {%0,%1,%2,%3};"
        : "+f"(d[0]), "+f"(d[1]), "+f"(d[2]), "+f"(d[3])
        : "r"(a[0]), "r"(a[1]), "r"(a[2]), "r"(a[3]), "r"(b0), "r"(b1));
}
__device__ __forceinline__ void cp16(uint32_t dst, const void* src) {
    asm volatile("cp.async.cg.shared.global [%0], [%1], 16;"
                 :: "r"(dst), "l"(src) : "memory");
}
#define CP_COMMIT() asm volatile("cp.async.commit_group;" ::: "memory")
#define CP_WAIT0()  asm volatile("cp.async.wait_group 0;" ::: "memory")

__device__ __forceinline__ ushort_t fp16hi(float v) {
    return __half_as_ushort(__float2half_rn(v));
}
__device__ __forceinline__ float fp16f(ushort_t u) {
    return __half2float(__ushort_as_half(u));
}

// ---------------------------------------------------------------------------
// prep kernels
// ---------------------------------------------------------------------------
__global__ __launch_bounds__(256) void prep_xh_kernel(
    const float* __restrict__ X, ushort_t* __restrict__ Xh)
{
    const size_t r = blockIdx.x;
    const int c4 = threadIdx.x << 2;
    float4 v = *(const float4*)(X + r * 1024 + c4);
    *(ushort4*)(Xh + r * 1024 + c4) =
        make_ushort4(fp16hi(v.x), fp16hi(v.y), fp16hi(v.z), fp16hi(v.w));
}

__global__ __launch_bounds__(256) void prep_wt_kernel(
    const float* __restrict__ W, ushort_t* __restrict__ Wt, int N)
{
    __shared__ float t[32][33];
    const int n0 = blockIdx.x << 5;
    const int k0 = blockIdx.y << 5;
    const int row = threadIdx.x >> 5;
    const int col = threadIdx.x & 31;
    #pragma unroll
    for (int p = 0; p < 4; ++p)
        t[row + p * 8][col] = W[(size_t)(k0 + row + p * 8) * N + n0 + col];
    __syncthreads();
    #pragma unroll
    for (int p = 0; p < 4; ++p) {
        int n = row + p * 8, k = col;
        Wt[(size_t)(n0 + n) * KW_ + k0 + k] = fp16hi(t[k][n]);
    }
}

// ---------------------------------------------------------------------------
// 1-term HMMA GEMM, BK=64 (two 32-col sub-tiles per stage), double-buffered.
// EPI: 0 -> fp32 C[M][N] ; 2 -> fp16 hi, row stride 3072
// ---------------------------------------------------------------------------
#define PITCH 40
#define ABUF  (128 * PITCH)        // halves per 32-col sub-tile
#define BUFH  (2 * ABUF)           // halves per array per stage (64 cols)
#define ROWBLK (16 * PITCH * 2)

template<int EPI>
__global__ __launch_bounds__(256, 2) void gemm_mma_kernel(
    const ushort_t* __restrict__ A, const ushort_t* __restrict__ Bh,
    const float* __restrict__ bias, void* __restrict__ Cout, int N, int n_base,
    int astride)
{
    extern __shared__ ushort_t gs[];
    ushort_t* sAh = gs;                  // [2 stages][2 subtiles][ABUF]
    ushort_t* sBs = gs + 2 * BUFH;

    const int tid  = threadIdx.x;
    const int lane = tid & 31, wid = tid >> 5;
    const int m0 = blockIdx.y << 7;
    const int n0 = n_base + (blockIdx.x << 7);
    const int wm = (wid & 1) << 6;
    const int wn = (wid >> 1) << 5;

    float acc[4][4][4];
    #pragma unroll
    for (int i = 0; i < 4; i++)
        #pragma unroll
        for (int j = 0; j < 4; j++)
            #pragma unroll
            for (int k = 0; k < 4; k++) acc[i][j][k] = 0.0f;

    const int r0s = tid >> 2, r1s = r0s + 64;
    const int js  = (tid & 3) << 3;
    const ushort_t* gA0 = A + (size_t)(m0 + r0s) * astride + js;
    const ushort_t* gA1 = A + (size_t)(m0 + r1s) * astride + js;
    const ushort_t* gB0 = Bh + (size_t)(n0 + r0s) * KW_ + js;
    const ushort_t* gB1 = Bh + (size_t)(n0 + r1s) * KW_ + js;
    const uint32_t so0b = (uint32_t)(r0s * PITCH + js) * 2;
    const uint32_t so1b = (uint32_t)(r1s * PITCH + js) * 2;

    const uint32_t uAh = smem_u32(sAh), uBs = smem_u32(sBs);
    const uint32_t BUF2 = BUFH * 2;                 // bytes per stage per array
    const uint32_t SUB2 = ABUF * 2;                 // bytes per sub-tile
    const uint32_t aoff = (uint32_t)((wm + (lane & 15)) * PITCH + (lane >> 4) * 8) * 2;
    const uint32_t boff = (uint32_t)((wn + (lane & 7) + ((lane >> 4) << 3)) * PITCH
                                     + ((lane >> 3) & 1) * 8) * 2;

    auto stage = [&](int cc) {                      // copy 64 k-cols
        const uint32_t ab = uAh + (uint32_t)(cc & 1) * BUF2;
        const uint32_t bb = uBs + (uint32_t)(cc & 1) * BUF2;
        #pragma unroll
        for (int sub = 0; sub < 2; ++sub) {
            const int kc = (cc << 6) + (sub << 5);
            const uint32_t sb = (uint32_t)sub * SUB2;
            cp16(ab + sb + so0b, gA0 + kc); cp16(ab + sb + so1b, gA1 + kc);
            cp16(bb + sb + so0b, gB0 + kc); cp16(bb + sb + so1b, gB1 + kc);
        }
        CP_COMMIT();
    };

    stage(0);
    CP_WAIT0();
    __syncthreads();

    for (int c = 0; c < 16; ++c) {
        if (c + 1 < 16) stage(c + 1);

        const uint32_t aSB = uAh + (uint32_t)(c & 1) * BUF2 + aoff;
        const uint32_t bSB = uBs + (uint32_t)(c & 1) * BUF2 + boff;

        #pragma unroll
        for (int sub = 0; sub < 2; ++sub) {
            const uint32_t aHB = aSB + (uint32_t)sub * SUB2;
            const uint32_t bBB = bSB + (uint32_t)sub * SUB2;

            uint32_t af[2][4][4], bf[2][2][4];
            ldsm4(bf[0][0], bBB);
            ldsm4(bf[0][1], bBB + ROWBLK);
            #pragma unroll
            for (int mi = 0; mi < 4; ++mi)
                ldsm4(af[0][mi], aHB + mi * ROWBLK);

            #pragma unroll
            for (int ph = 0; ph < 2; ++ph) {
                if (ph == 0) {
                    ldsm4(bf[1][0], bBB + 32);
                    ldsm4(bf[1][1], bBB + ROWBLK + 32);
                    #pragma unroll
                    for (int mi = 0; mi < 4; ++mi)
                        ldsm4(af[1][mi], aHB + mi * ROWBLK + 32);
                }
                #pragma unroll
                for (int mi = 0; mi < 4; ++mi) {
                    mma16816(acc[mi][0], af[ph][mi], bf[ph][0][0], bf[ph][0][1]);
                    mma16816(acc[mi][1], af[ph][mi], bf[ph][0][2], bf[ph][0][3]);
                    mma16816(acc[mi][2], af[ph][mi], bf[ph][1][0], bf[ph][1][1]);
                    mma16816(acc[mi][3], af[ph][mi], bf[ph][1][2], bf[ph][1][3]);
                }
            }
        }

        if (c + 1 < 16) CP_WAIT0();
        __syncthreads();
    }

    const int g  = lane >> 2;
    const int tg = (lane & 3) << 1;
    #pragma unroll
    for (int ni = 0; ni < 4; ++ni) {
        int col = n0 + wn + ni * 8 + tg;
        float2 bv = *(const float2*)(bias + col);
        #pragma unroll
        for (int mi = 0; mi < 4; ++mi) {
            int r0 = m0 + wm + mi * 16 + g;
            float a0 = acc[mi][ni][0] + bv.x, a1 = acc[mi][ni][1] + bv.y;
            float a2 = acc[mi][ni][2] + bv.x, a3 = acc[mi][ni][3] + bv.y;
            if (EPI == 0) {
                float* C = (float*)Cout;
                *(float2*)&C[(size_t)r0 * N + col]       = make_float2(a0, a1);
                *(float2*)&C[(size_t)(r0 + 8) * N + col] = make_float2(a2, a3);
            } else {
                ushort_t* C = (ushort_t*)Cout;
                *(ushort2*)&C[(size_t)r0 * C3_ + col] =
                    make_ushort2(fp16hi(a0), fp16hi(a1));
                *(ushort2*)&C[(size_t)(r0 + 8) * C3_ + col] =
                    make_ushort2(fp16hi(a2), fp16hi(a3));
            }
        }
    }
}

// ---------------------------------------------------------------------------
// Fused attention (R14 proven version): q-block 32, 256 threads, 2 CTAs/SM.
// ---------------------------------------------------------------------------
struct SmemAttn6 {
    float l_red[32];
    float l_inv[32];
    ushort_t S[32 * PS_];                                 // 66048 B
    union {
        struct { ushort_t Qh[32 * PQ_]; ushort_t Kh[2][128 * PQ_]; } p1;
        struct { ushort_t Vs[2][128 * PQ_]; } p2;
    } u;
};

__global__ __launch_bounds__(256, 2) void fused_attn_mma_kernel(
    const ushort_t* __restrict__ QKVh, ushort_t* __restrict__ Yh)
{
    extern __shared__ char smem_raw[];
    SmemAttn6& sm = *reinterpret_cast<SmemAttn6*>(smem_raw);

    const int qb = blockIdx.x;       // 0..31
    const int bh = blockIdx.y;       // 0..127
    const int b  = bh >> 4;
    const int h  = bh & 15;
    const int hc = h * HD_;
    const ushort_t* base = QKVh + (size_t)b * T_ * C3_;

    const int tid  = threadIdx.x;
    const int lane = tid & 31, wid = tid >> 5;
    const int q0   = qb << 5;
    const int g    = lane >> 2;

    if (tid < 32) sm.l_red[tid] = 0.0f;

    const uint32_t sQh = smem_u32(sm.u.p1.Qh);
    const uint32_t sK0 = smem_u32(sm.u.p1.Kh[0]);
    const uint32_t sS  = smem_u32(sm.S);
    const uint32_t KBUF = 128 * PQ_ * 2;

    {
        int r = tid >> 3, j = tid & 7;
        cp16(sQh + (uint32_t)(r * PQ_ + (j << 3)) * 2,
             base + (size_t)(q0 + r) * C3_ + hc + (j << 3));
    }
    #pragma unroll
    for (int l = 0; l < 4; ++l) {
        int c = tid + (l << 8);
        int r = c >> 3, j = c & 7;
        cp16(sK0 + (uint32_t)(r * PQ_ + (j << 3)) * 2,
             base + (size_t)r * C3_ + 1024 + hc + (j << 3));
    }
    CP_COMMIT();
    CP_WAIT0();
    __syncthreads();

    const int wm = (wid & 1) << 4;
    const int wn = (wid >> 1) << 5;
    const uint32_t aoff = (uint32_t)((wm + (lane & 15)) * PQ_ + (lane >> 4) * 8) * 2;
    const uint32_t boff = (uint32_t)((wn + (lane & 7) + ((lane >> 4) << 3)) * PQ_
                                     + ((lane >> 3) & 1) * 8) * 2;

    float lsum[2] = {0.0f, 0.0f};

    for (int t = 0; t < 8; ++t) {
        const int k0 = t << 7;
        const int buf = t & 1;
        if (t + 1 < 8) {
            const uint32_t dstK = sK0 + (uint32_t)(1 - buf) * KBUF;
            #pragma unroll
            for (int l = 0; l < 4; ++l) {
                int c = tid + (l << 8);
                int r = c >> 3, j = c & 7;
                cp16(dstK + (uint32_t)(r * PQ_ + (j << 3)) * 2,
                     base + (size_t)(k0 + 128 + r) * C3_ + 1024 + hc + (j << 3));
            }
            CP_COMMIT();
        }

        const uint32_t sKb = sK0 + (uint32_t)buf * KBUF;

        float acc[4][4];
        #pragma unroll
        for (int j = 0; j < 4; ++j)
            #pragma unroll
            for (int k = 0; k < 4; ++k) acc[j][k] = 0.0f;

        #pragma unroll
        for (int ks = 0; ks < 4; ++ks) {
            uint32_t bf[2][4];
            ldsm4(bf[0], sKb + boff + ks * 32);
            ldsm4(bf[1], sKb + boff + (16 * PQ_ * 2) + ks * 32);
            uint32_t af[4];
            ldsm4(af, sQh + aoff + ks * 32);
            mma16816(acc[0], af, bf[0][0], bf[0][1]);
            mma16816(acc[1], af, bf[0][2], bf[0][3]);
            mma16816(acc[2], af, bf[1][0], bf[1][1]);
            mma16816(acc[3], af, bf[1][2], bf[1][3]);
        }

        #pragma unroll
        for (int ni = 0; ni < 4; ++ni) {
            float e0 = __expf(acc[ni][0] * 0.125f);
            float e1 = __expf(acc[ni][1] * 0.125f);
            float e2 = __expf(acc[ni][2] * 0.125f);
            float e3 = __expf(acc[ni][3] * 0.125f);
            lsum[0] += e0 + e1;
            lsum[1] += e2 + e3;
            int col = k0 + wn + ni * 8 + ((lane & 3) << 1);
            int r0  = wm + g;
            *(ushort2*)&sm.S[(size_t)r0 * PS_ + col] =
                make_ushort2(fp16hi(e0), fp16hi(e1));
            *(ushort2*)&sm.S[(size_t)(r0 + 8) * PS_ + col] =
                make_ushort2(fp16hi(e2), fp16hi(e3));
        }

        if (t + 1 < 8) CP_WAIT0();
        __syncthreads();
    }

    #pragma unroll
    for (int i = 0; i < 2; i++) {
        float v = lsum[i];
        v += __shfl_xor_sync(0xFFFFFFFFu, v, 1);
        v += __shfl_xor_sync(0xFFFFFFFFu, v, 2);
        if ((lane & 3) == 0)
            atomicAdd(&sm.l_red[wm + g + i * 8], v);
    }
    __syncthreads();
    if (tid < 32) sm.l_inv[tid] = 1.0f / sm.l_red[tid];
    __syncthreads();

    const uint32_t sV0 = smem_u32(sm.u.p2.Vs[0]);
    #pragma unroll
    for (int l = 0; l < 4; ++l) {
        int c = tid + (l << 8);
        int r = c >> 3, j = c & 7;
        cp16(sV0 + (uint32_t)(r * PQ_ + (j << 3)) * 2,
             base + (size_t)r * C3_ + 2048 + hc + (j << 3));
    }
    CP_COMMIT();

    #pragma unroll
    for (int l = 0; l < 16; ++l) {
        int idx = tid + (l << 8);
        int r   = idx >> 7;
        int c8  = (idx & 127) << 3;
        ushort_t* p = &sm.S[(size_t)r * PS_ + c8];
        uint4 eu = *(uint4*)p;
        float iv = sm.l_inv[r];
        ushort_t* ep = (ushort_t*)&eu;
        #pragma unroll
        for (int i = 0; i < 8; ++i)
            ep[i] = fp16hi(fmaxf(fmaf(fp16f(ep[i]), iv, -TH_), 0.0f));
        *(uint4*)p = eu;
    }
    CP_WAIT0();
    __syncthreads();

    const int wm2 = (wid & 1) << 4;
    const int wn2 = (wid >> 1) << 4;
    const uint32_t aoff2 = (uint32_t)((wm2 + (lane & 15)) * PS_ + (lane >> 4) * 8) * 2;
    const uint32_t boff2t = (uint32_t)((lane & 15) * PQ_ + wn2 + ((lane >> 4) << 3)) * 2;

    float accy[2][4];
    #pragma unroll
    for (int j = 0; j < 2; ++j)
        #pragma unroll
        for (int k = 0; k < 4; ++k) accy[j][k] = 0.0f;

    for (int t = 0; t < 8; ++t) {
        const int kc = t << 7;
        const int buf = t & 1;
        if (t + 1 < 8) {
            const uint32_t dstV = sV0 + (uint32_t)(1 - buf) * KBUF;
            #pragma unroll
            for (int l = 0; l < 4; ++l) {
                int c = tid + (l << 8);
                int r = c >> 3, j = c & 7;
                cp16(dstV + (uint32_t)(r * PQ_ + (j << 3)) * 2,
                     base + (size_t)(kc + 128 + r) * C3_ + 2048 + hc + (j << 3));
            }
            CP_COMMIT();
        }

        const uint32_t sVb = sV0 + (uint32_t)buf * KBUF;

        #pragma unroll
        for (int ks = 0; ks < 8; ++ks) {
            uint32_t bf[4];
            ldsm4t(bf, sVb + boff2t + ks * (16 * PQ_ * 2));
            uint32_t af[4];
            ldsm4(af, sS + aoff2 + (uint32_t)kc * 2 + ks * 32);
            mma16816(accy[0], af, bf[0], bf[1]);
            mma16816(accy[1], af, bf[2], bf[3]);
        }

        if (t + 1 < 8) CP_WAIT0();
        __syncthreads();
    }

    #pragma unroll
    for (int ni = 0; ni < 2; ++ni) {
        int ch = hc + wn2 + ni * 8 + ((lane & 3) << 1);
        #pragma unroll
        for (int hv = 0; hv < 2; ++hv) {
            int rq = q0 + wm2 + g + hv * 8;
            size_t rg = ((size_t)b * T_ + rq) * C_;
            *(ushort2*)&Yh[rg + ch] =
                make_ushort2(fp16hi(accy[ni][hv * 2 + 0]),
                             fp16hi(accy[ni][hv * 2 + 1]));
        }
    }
}

// ---------------------------------------------------------------------------
extern "C" void kernel_launch(void* const* d_in, const int* in_sizes, int n_in,
                              void* d_out, int out_size)
{
    const float* x      = (const float*)d_in[0];
    const float* w_attn = (const float*)d_in[1];
    const float* b_attn = (const float*)d_in[2];
    const float* w_proj = (const float*)d_in[3];
    const float* b_proj = (const float*)d_in[4];
    float* out = (float*)d_out;

    ushort_t *qkvh, *yh, *xh, *wa, *wp;
    cudaGetSymbolAddress((void**)&qkvh, g_qkvh);
    cudaGetSymbolAddress((void**)&yh,   g_yh);
    cudaGetSymbolAddress((void**)&xh,   g_xh);
    cudaGetSymbolAddress((void**)&wa,   g_wa);
    cudaGetSymbolAddress((void**)&wp,   g_wp);

    const int gsmem = 8 * ABUF * 2;   // 81920 B (2 stages x 2 subtiles x A,B)
    cudaFuncSetAttribute(gemm_mma_kernel<2>,
                         cudaFuncAttributeMaxDynamicSharedMemorySize, gsmem);
    cudaFuncSetAttribute(gemm_mma_kernel<0>,
                         cudaFuncAttributeMaxDynamicSharedMemorySize, gsmem);
    cudaFuncSetAttribute(fused_attn_mma_kernel,
                         cudaFuncAttributeMaxDynamicSharedMemorySize,
                         (int)sizeof(SmemAttn6));

    // prep
    prep_xh_kernel<<<B_ * T_, 256>>>(x, xh);
    prep_wt_kernel<<<dim3(C3_ / 32, C_ / 32), 256>>>(w_attn, wa, C3_);
    prep_wt_kernel<<<dim3(C_ / 32, C_ / 32), 256>>>(w_proj, wp, C_);

    // 1) QKV projection (1-term, fp16-hi out)
    gemm_mma_kernel<2><<<dim3(24, 64), 256, gsmem>>>(
        xh, wa, b_attn, qkvh, C3_, 0, C_);

    // 2) fused attention (R14 version)
    fused_attn_mma_kernel<<<dim3(32, 128), 256, sizeof(SmemAttn6)>>>(qkvh, yh);

    // 3) output projection (fp32 out)
    gemm_mma_kernel<0><<<dim3(8, 64), 256, gsmem>>>(
        yh, wp, b_proj, out, C_, 0, C_);
}

// round 16
// speedup vs baseline: 1.0425x; 1.0425x over previous
#include <cuda_runtime.h>
#include <cuda_fp16.h>
#include <cstddef>
#include <cstdint>

#define B_   8
#define T_   1024
#define C_   1024
#define H_   16
#define HD_  64
#define BH_  (B_ * H_)          // 128
#define C3_  (3 * C_)           // 3072
#define KW_  1024               // K for all GEMMs (hi-only)
#define TH_  0.001f
#define PQ_  72                 // staging pitch (halves) for 64-wide tiles
#define PS_  1032               // S panel pitch (halves): 2064 B rows

using ushort_t = unsigned short;

// ---------------- scratch (static device globals) ----------------
__device__ __align__(16) ushort_t g_qkvh[(size_t)B_ * T_ * C3_];        // fp16 hi QKV
__device__ __align__(16) ushort_t g_yh[(size_t)B_ * T_ * C_];           // fp16 hi Y
__device__ __align__(16) ushort_t g_xh[(size_t)B_ * T_ * C_];           // fp16 hi x
__device__ __align__(16) ushort_t g_wa[(size_t)C3_ * KW_];              // w_attn^T hi
__device__ __align__(16) ushort_t g_wp[(size_t)C_ * KW_];               // w_proj^T hi

// ---------------- helpers ----------------
__device__ __forceinline__ uint32_t smem_u32(const void* p) {
    uint32_t a;
    asm("{ .reg .u64 t; cvta.to.shared.u64 t, %1; cvt.u32.u64 %0, t; }"
        : "=r"(a) : "l"(p));
    return a;
}
__device__ __forceinline__ void ldsm4(uint32_t (&r)[4], uint32_t addr) {
    asm volatile("ldmatrix.sync.aligned.m8n8.x4.shared.b16 {%0,%1,%2,%3}, [%4];"
        : "=r"(r[0]), "=r"(r[1]), "=r"(r[2]), "=r"(r[3]) : "r"(addr));
}
__device__ __forceinline__ void ldsm4t(uint32_t (&r)[4], uint32_t addr) {
    asm volatile("ldmatrix.sync.aligned.m8n8.x4.trans.shared.b16 {%0,%1,%2,%3}, [%4];"
        : "=r"(r[0]), "=r"(r[1]), "=r"(r[2]), "=r"(r[3]) : "r"(addr));
}
__device__ __forceinline__ void mma16816(float (&d)[4], const uint32_t (&a)[4],
                                         uint32_t b0, uint32_t b1) {
    asm volatile(
        "mma.sync.aligned.m16n8k16.row.col.f32.f16.f16.f32 "
        "{%0,%1,%2,%3}, {%4,%5,%6,%7}, {%8,%9}, {%0,%1,%2,%3};"
        : "+f"(d[0]), "+f"(d[1]), "+f"(d[2]), "+f"(d[3])
        : "r"(a[0]), "r"(a[1]), "r"(a[2]), "r"(a[3]), "r"(b0), "r"(b1));
}
__device__ __forceinline__ void cp16(uint32_t dst, const void* src) {
    asm volatile("cp.async.cg.shared.global [%0], [%1], 16;"
                 :: "r"(dst), "l"(src) : "memory");
}
#define CP_COMMIT() asm volatile("cp.async.commit_group;" ::: "memory")
#define CP_WAIT0()  asm volatile("cp.async.wait_group 0;" ::: "memory")

__device__ __forceinline__ ushort_t fp16hi(float v) {
    return __half_as_ushort(__float2half_rn(v));
}

// ---------------------------------------------------------------------------
// prep kernels
// ---------------------------------------------------------------------------
__global__ __launch_bounds__(256) void prep_xh_kernel(
    const float* __restrict__ X, ushort_t* __restrict__ Xh)
{
    const size_t r = blockIdx.x;
    const int c4 = threadIdx.x << 2;
    float4 v = *(const float4*)(X + r * 1024 + c4);
    *(ushort4*)(Xh + r * 1024 + c4) =
        make_ushort4(fp16hi(v.x), fp16hi(v.y), fp16hi(v.z), fp16hi(v.w));
}

__global__ __launch_bounds__(256) void prep_wt_kernel(
    const float* __restrict__ W, ushort_t* __restrict__ Wt, int N)
{
    __shared__ float t[32][33];
    const int n0 = blockIdx.x << 5;
    const int k0 = blockIdx.y << 5;
    const int row = threadIdx.x >> 5;
    const int col = threadIdx.x & 31;
    #pragma unroll
    for (int p = 0; p < 4; ++p)
        t[row + p * 8][col] = W[(size_t)(k0 + row + p * 8) * N + n0 + col];
    __syncthreads();
    #pragma unroll
    for (int p = 0; p < 4; ++p) {
        int n = row + p * 8, k = col;
        Wt[(size_t)(n0 + n) * KW_ + k0 + k] = fp16hi(t[k][n]);
    }
}

// ---------------------------------------------------------------------------
// 1-term HMMA GEMM (R14-exact: BK=32, 2-stage cp.async pipeline).
// EPI: 0 -> fp32 C[M][N] ; 2 -> fp16 hi, row stride 3072
// ---------------------------------------------------------------------------
#define PITCH 40
#define ABUF  (128 * PITCH)
#define ROWBLK (16 * PITCH * 2)

template<int EPI>
__global__ __launch_bounds__(256, 2) void gemm_mma_kernel(
    const ushort_t* __restrict__ A, const ushort_t* __restrict__ Bh,
    const float* __restrict__ bias, void* __restrict__ Cout, int N, int n_base,
    int astride)
{
    extern __shared__ ushort_t gs[];
    ushort_t* sAh = gs;
    ushort_t* sBs = gs + 2 * ABUF;

    const int tid  = threadIdx.x;
    const int lane = tid & 31, wid = tid >> 5;
    const int m0 = blockIdx.y << 7;
    const int n0 = n_base + (blockIdx.x << 7);
    const int wm = (wid & 1) << 6;
    const int wn = (wid >> 1) << 5;

    float acc[4][4][4];
    #pragma unroll
    for (int i = 0; i < 4; i++)
        #pragma unroll
        for (int j = 0; j < 4; j++)
            #pragma unroll
            for (int k = 0; k < 4; k++) acc[i][j][k] = 0.0f;

    const int r0s = tid >> 2, r1s = r0s + 64;
    const int js  = (tid & 3) << 3;
    const ushort_t* gA0 = A + (size_t)(m0 + r0s) * astride + js;
    const ushort_t* gA1 = A + (size_t)(m0 + r1s) * astride + js;
    const ushort_t* gB0 = Bh + (size_t)(n0 + r0s) * KW_ + js;
    const ushort_t* gB1 = Bh + (size_t)(n0 + r1s) * KW_ + js;
    const uint32_t so0b = (uint32_t)(r0s * PITCH + js) * 2;
    const uint32_t so1b = (uint32_t)(r1s * PITCH + js) * 2;

    const uint32_t uAh = smem_u32(sAh), uBs = smem_u32(sBs);
    const uint32_t AB2 = ABUF * 2;
    const uint32_t aoff = (uint32_t)((wm + (lane & 15)) * PITCH + (lane >> 4) * 8) * 2;
    const uint32_t boff = (uint32_t)((wn + (lane & 7) + ((lane >> 4) << 3)) * PITCH
                                     + ((lane >> 3) & 1) * 8) * 2;

    cp16(uAh + so0b, gA0); cp16(uAh + so1b, gA1);
    cp16(uBs + so0b, gB0); cp16(uBs + so1b, gB1);
    CP_COMMIT();
    CP_WAIT0();
    __syncthreads();

    for (int c = 0; c < 32; ++c) {
        const int buf = c & 1;
        if (c + 1 < 32) {
            const int kc = (c + 1) << 5;
            const uint32_t nb = (uint32_t)(1 - buf) * AB2;
            cp16(uAh + nb + so0b, gA0 + kc);
            cp16(uAh + nb + so1b, gA1 + kc);
            cp16(uBs + nb + so0b, gB0 + kc);
            cp16(uBs + nb + so1b, gB1 + kc);
            CP_COMMIT();
        }

        const uint32_t aHB = uAh + buf * AB2 + aoff;
        const uint32_t bBB = uBs + buf * AB2 + boff;

        uint32_t af[2][4][4], bf[2][2][4];
        ldsm4(bf[0][0], bBB);
        ldsm4(bf[0][1], bBB + ROWBLK);
        #pragma unroll
        for (int mi = 0; mi < 4; ++mi)
            ldsm4(af[0][mi], aHB + mi * ROWBLK);

        #pragma unroll
        for (int ph = 0; ph < 2; ++ph) {
            if (ph == 0) {
                ldsm4(bf[1][0], bBB + 32);
                ldsm4(bf[1][1], bBB + ROWBLK + 32);
                #pragma unroll
                for (int mi = 0; mi < 4; ++mi)
                    ldsm4(af[1][mi], aHB + mi * ROWBLK + 32);
            }
            #pragma unroll
            for (int mi = 0; mi < 4; ++mi) {
                mma16816(acc[mi][0], af[ph][mi], bf[ph][0][0], bf[ph][0][1]);
                mma16816(acc[mi][1], af[ph][mi], bf[ph][0][2], bf[ph][0][3]);
                mma16816(acc[mi][2], af[ph][mi], bf[ph][1][0], bf[ph][1][1]);
                mma16816(acc[mi][3], af[ph][mi], bf[ph][1][2], bf[ph][1][3]);
            }
        }

        if (c + 1 < 32) CP_WAIT0();
        __syncthreads();
    }

    const int g  = lane >> 2;
    const int tg = (lane & 3) << 1;
    #pragma unroll
    for (int ni = 0; ni < 4; ++ni) {
        int col = n0 + wn + ni * 8 + tg;
        float2 bv = *(const float2*)(bias + col);
        #pragma unroll
        for (int mi = 0; mi < 4; ++mi) {
            int r0 = m0 + wm + mi * 16 + g;
            float a0 = acc[mi][ni][0] + bv.x, a1 = acc[mi][ni][1] + bv.y;
            float a2 = acc[mi][ni][2] + bv.x, a3 = acc[mi][ni][3] + bv.y;
            if (EPI == 0) {
                float* C = (float*)Cout;
                *(float2*)&C[(size_t)r0 * N + col]       = make_float2(a0, a1);
                *(float2*)&C[(size_t)(r0 + 8) * N + col] = make_float2(a2, a3);
            } else {
                ushort_t* C = (ushort_t*)Cout;
                *(ushort2*)&C[(size_t)r0 * C3_ + col] =
                    make_ushort2(fp16hi(a0), fp16hi(a1));
                *(ushort2*)&C[(size_t)(r0 + 8) * C3_ + col] =
                    make_ushort2(fp16hi(a2), fp16hi(a3));
            }
        }
    }
}

// ---------------------------------------------------------------------------
// Fused attention (R14 structure): q-block 32, 256 threads, 2 CTAs/SM.
// Epilogues use packed half2 math.
// ---------------------------------------------------------------------------
struct SmemAttn6 {
    float l_red[32];
    float l_inv[32];
    ushort_t S[32 * PS_];                                 // 66048 B
    union {
        struct { ushort_t Qh[32 * PQ_]; ushort_t Kh[2][128 * PQ_]; } p1;
        struct { ushort_t Vs[2][128 * PQ_]; } p2;
    } u;
};

__global__ __launch_bounds__(256, 2) void fused_attn_mma_kernel(
    const ushort_t* __restrict__ QKVh, ushort_t* __restrict__ Yh)
{
    extern __shared__ char smem_raw[];
    SmemAttn6& sm = *reinterpret_cast<SmemAttn6*>(smem_raw);

    const int qb = blockIdx.x;       // 0..31
    const int bh = blockIdx.y;       // 0..127
    const int b  = bh >> 4;
    const int h  = bh & 15;
    const int hc = h * HD_;
    const ushort_t* base = QKVh + (size_t)b * T_ * C3_;

    const int tid  = threadIdx.x;
    const int lane = tid & 31, wid = tid >> 5;
    const int q0   = qb << 5;
    const int g    = lane >> 2;

    if (tid < 32) sm.l_red[tid] = 0.0f;

    const uint32_t sQh = smem_u32(sm.u.p1.Qh);
    const uint32_t sK0 = smem_u32(sm.u.p1.Kh[0]);
    const uint32_t sS  = smem_u32(sm.S);
    const uint32_t KBUF = 128 * PQ_ * 2;

    {
        int r = tid >> 3, j = tid & 7;
        cp16(sQh + (uint32_t)(r * PQ_ + (j << 3)) * 2,
             base + (size_t)(q0 + r) * C3_ + hc + (j << 3));
    }
    #pragma unroll
    for (int l = 0; l < 4; ++l) {
        int c = tid + (l << 8);
        int r = c >> 3, j = c & 7;
        cp16(sK0 + (uint32_t)(r * PQ_ + (j << 3)) * 2,
             base + (size_t)r * C3_ + 1024 + hc + (j << 3));
    }
    CP_COMMIT();
    CP_WAIT0();
    __syncthreads();

    const int wm = (wid & 1) << 4;
    const int wn = (wid >> 1) << 5;
    const uint32_t aoff = (uint32_t)((wm + (lane & 15)) * PQ_ + (lane >> 4) * 8) * 2;
    const uint32_t boff = (uint32_t)((wn + (lane & 7) + ((lane >> 4) << 3)) * PQ_
                                     + ((lane >> 3) & 1) * 8) * 2;

    float lsum[2] = {0.0f, 0.0f};

    for (int t = 0; t < 8; ++t) {
        const int k0 = t << 7;
        const int buf = t & 1;
        if (t + 1 < 8) {
            const uint32_t dstK = sK0 + (uint32_t)(1 - buf) * KBUF;
            #pragma unroll
            for (int l = 0; l < 4; ++l) {
                int c = tid + (l << 8);
                int r = c >> 3, j = c & 7;
                cp16(dstK + (uint32_t)(r * PQ_ + (j << 3)) * 2,
                     base + (size_t)(k0 + 128 + r) * C3_ + 1024 + hc + (j << 3));
            }
            CP_COMMIT();
        }

        const uint32_t sKb = sK0 + (uint32_t)buf * KBUF;

        float acc[4][4];
        #pragma unroll
        for (int j = 0; j < 4; ++j)
            #pragma unroll
            for (int k = 0; k < 4; ++k) acc[j][k] = 0.0f;

        #pragma unroll
        for (int ks = 0; ks < 4; ++ks) {
            uint32_t bf[2][4];
            ldsm4(bf[0], sKb + boff + ks * 32);
            ldsm4(bf[1], sKb + boff + (16 * PQ_ * 2) + ks * 32);
            uint32_t af[4];
            ldsm4(af, sQh + aoff + ks * 32);
            mma16816(acc[0], af, bf[0][0], bf[0][1]);
            mma16816(acc[1], af, bf[0][2], bf[0][3]);
            mma16816(acc[2], af, bf[1][0], bf[1][1]);
            mma16816(acc[3], af, bf[1][2], bf[1][3]);
        }

        // exp epilogue -> smem S panel (packed cvt), fp32 row sums
        #pragma unroll
        for (int ni = 0; ni < 4; ++ni) {
            float e0 = __expf(acc[ni][0] * 0.125f);
            float e1 = __expf(acc[ni][1] * 0.125f);
            float e2 = __expf(acc[ni][2] * 0.125f);
            float e3 = __expf(acc[ni][3] * 0.125f);
            lsum[0] += e0 + e1;
            lsum[1] += e2 + e3;
            int col = k0 + wn + ni * 8 + ((lane & 3) << 1);
            int r0  = wm + g;
            *(__half2*)&sm.S[(size_t)r0 * PS_ + col]       = __floats2half2_rn(e0, e1);
            *(__half2*)&sm.S[(size_t)(r0 + 8) * PS_ + col] = __floats2half2_rn(e2, e3);
        }

        if (t + 1 < 8) CP_WAIT0();
        __syncthreads();
    }

    #pragma unroll
    for (int i = 0; i < 2; i++) {
        float v = lsum[i];
        v += __shfl_xor_sync(0xFFFFFFFFu, v, 1);
        v += __shfl_xor_sync(0xFFFFFFFFu, v, 2);
        if ((lane & 3) == 0)
            atomicAdd(&sm.l_red[wm + g + i * 8], v);
    }
    __syncthreads();
    if (tid < 32) sm.l_inv[tid] = 1.0f / sm.l_red[tid];
    __syncthreads();

    const uint32_t sV0 = smem_u32(sm.u.p2.Vs[0]);
    #pragma unroll
    for (int l = 0; l < 4; ++l) {
        int c = tid + (l << 8);
        int r = c >> 3, j = c & 7;
        cp16(sV0 + (uint32_t)(r * PQ_ + (j << 3)) * 2,
             base + (size_t)r * C3_ + 2048 + hc + (j << 3));
    }
    CP_COMMIT();

    // in-place transform: P = relu(e * linv - TH), packed half2
    {
        const __half2 th2 = __float2half2_rn(TH_);
        const __half2 z2  = __float2half2_rn(0.0f);
        #pragma unroll
        for (int l = 0; l < 16; ++l) {
            int idx = tid + (l << 8);
            int r   = idx >> 7;
            int c8  = (idx & 127) << 3;
            __half2* p = (__half2*)&sm.S[(size_t)r * PS_ + c8];
            const __half2 iv2 = __float2half2_rn(sm.l_inv[r]);
            __half2 v0 = p[0], v1 = p[1], v2 = p[2], v3 = p[3];
            v0 = __hmax2(__hsub2(__hmul2(v0, iv2), th2), z2);
            v1 = __hmax2(__hsub2(__hmul2(v1, iv2), th2), z2);
            v2 = __hmax2(__hsub2(__hmul2(v2, iv2), th2), z2);
            v3 = __hmax2(__hsub2(__hmul2(v3, iv2), th2), z2);
            p[0] = v0; p[1] = v1; p[2] = v2; p[3] = v3;
        }
    }
    CP_WAIT0();
    __syncthreads();

    const int wm2 = (wid & 1) << 4;
    const int wn2 = (wid >> 1) << 4;
    const uint32_t aoff2 = (uint32_t)((wm2 + (lane & 15)) * PS_ + (lane >> 4) * 8) * 2;
    const uint32_t boff2t = (uint32_t)((lane & 15) * PQ_ + wn2 + ((lane >> 4) << 3)) * 2;

    float accy[2][4];
    #pragma unroll
    for (int j = 0; j < 2; ++j)
        #pragma unroll
        for (int k = 0; k < 4; ++k) accy[j][k] = 0.0f;

    for (int t = 0; t < 8; ++t) {
        const int kc = t << 7;
        const int buf = t & 1;
        if (t + 1 < 8) {
            const uint32_t dstV = sV0 + (uint32_t)(1 - buf) * KBUF;
            #pragma unroll
            for (int l = 0; l < 4; ++l) {
                int c = tid + (l << 8);
                int r = c >> 3, j = c & 7;
                cp16(dstV + (uint32_t)(r * PQ_ + (j << 3)) * 2,
                     base + (size_t)(kc + 128 + r) * C3_ + 2048 + hc + (j << 3));
            }
            CP_COMMIT();
        }

        const uint32_t sVb = sV0 + (uint32_t)buf * KBUF;

        #pragma unroll
        for (int ks = 0; ks < 8; ++ks) {
            uint32_t bf[4];
            ldsm4t(bf, sVb + boff2t + ks * (16 * PQ_ * 2));
            uint32_t af[4];
            ldsm4(af, sS + aoff2 + (uint32_t)kc * 2 + ks * 32);
            mma16816(accy[0], af, bf[0], bf[1]);
            mma16816(accy[1], af, bf[2], bf[3]);
        }

        if (t + 1 < 8) CP_WAIT0();
        __syncthreads();
    }

    #pragma unroll
    for (int ni = 0; ni < 2; ++ni) {
        int ch = hc + wn2 + ni * 8 + ((lane & 3) << 1);
        #pragma unroll
        for (int hv = 0; hv < 2; ++hv) {
            int rq = q0 + wm2 + g + hv * 8;
            size_t rg = ((size_t)b * T_ + rq) * C_;
            *(__half2*)&Yh[rg + ch] =
                __floats2half2_rn(accy[ni][hv * 2 + 0], accy[ni][hv * 2 + 1]);
        }
    }
}

// ---------------------------------------------------------------------------
extern "C" void kernel_launch(void* const* d_in, const int* in_sizes, int n_in,
                              void* d_out, int out_size)
{
    const float* x      = (const float*)d_in[0];
    const float* w_attn = (const float*)d_in[1];
    const float* b_attn = (const float*)d_in[2];
    const float* w_proj = (const float*)d_in[3];
    const float* b_proj = (const float*)d_in[4];
    float* out = (float*)d_out;

    ushort_t *qkvh, *yh, *xh, *wa, *wp;
    cudaGetSymbolAddress((void**)&qkvh, g_qkvh);
    cudaGetSymbolAddress((void**)&yh,   g_yh);
    cudaGetSymbolAddress((void**)&xh,   g_xh);
    cudaGetSymbolAddress((void**)&wa,   g_wa);
    cudaGetSymbolAddress((void**)&wp,   g_wp);

    const int gsmem = 4 * ABUF * 2;   // 40960 B (2-stage A + B)
    cudaFuncSetAttribute(gemm_mma_kernel<2>,
                         cudaFuncAttributeMaxDynamicSharedMemorySize, gsmem);
    cudaFuncSetAttribute(gemm_mma_kernel<0>,
                         cudaFuncAttributeMaxDynamicSharedMemorySize, gsmem);
    cudaFuncSetAttribute(fused_attn_mma_kernel,
                         cudaFuncAttributeMaxDynamicSharedMemorySize,
                         (int)sizeof(SmemAttn6));

    // prep
    prep_xh_kernel<<<B_ * T_, 256>>>(x, xh);
    prep_wt_kernel<<<dim3(C3_ / 32, C_ / 32), 256>>>(w_attn, wa, C3_);
    prep_wt_kernel<<<dim3(C_ / 32, C_ / 32), 256>>>(w_proj, wp, C_);

    // 1) QKV projection (1-term, fp16-hi out)
    gemm_mma_kernel<2><<<dim3(24, 64), 256, gsmem>>>(
        xh, wa, b_attn, qkvh, C3_, 0, C_);

    // 2) fused attention
    fused_attn_mma_kernel<<<dim3(32, 128), 256, sizeof(SmemAttn6)>>>(qkvh, yh);

    // 3) output projection (fp32 out)
    gemm_mma_kernel<0><<<dim3(8, 64), 256, gsmem>>>(
        yh, wp, b_proj, out, C_, 0, C_);
}

// round 17
// speedup vs baseline: 1.0786x; 1.0347x over previous
#include <cuda_runtime.h>
#include <cuda_fp16.h>
#include <cstddef>
#include <cstdint>

#define B_   8
#define T_   1024
#define C_   1024
#define H_   16
#define HD_  64
#define BH_  (B_ * H_)          // 128
#define C3_  (3 * C_)           // 3072
#define KW_  1024               // K for all GEMMs (hi-only)
#define TH_  0.001f
#define PQ_  72                 // staging pitch (halves) for 64-wide tiles
#define PS_  1032               // S panel pitch (halves): 2064 B rows

using ushort_t = unsigned short;

// ---------------- scratch (static device globals) ----------------
__device__ __align__(16) ushort_t g_qkvh[(size_t)B_ * T_ * C3_];        // fp16 hi QKV
__device__ __align__(16) ushort_t g_yh[(size_t)B_ * T_ * C_];           // fp16 hi Y
__device__ __align__(16) ushort_t g_xh[(size_t)B_ * T_ * C_];           // fp16 hi x
__device__ __align__(16) ushort_t g_wa[(size_t)C3_ * KW_];              // w_attn^T hi
__device__ __align__(16) ushort_t g_wp[(size_t)C_ * KW_];               // w_proj^T hi

// ---------------- helpers ----------------
__device__ __forceinline__ uint32_t smem_u32(const void* p) {
    uint32_t a;
    asm("{ .reg .u64 t; cvta.to.shared.u64 t, %1; cvt.u32.u64 %0, t; }"
        : "=r"(a) : "l"(p));
    return a;
}
__device__ __forceinline__ void ldsm4(uint32_t (&r)[4], uint32_t addr) {
    asm volatile("ldmatrix.sync.aligned.m8n8.x4.shared.b16 {%0,%1,%2,%3}, [%4];"
        : "=r"(r[0]), "=r"(r[1]), "=r"(r[2]), "=r"(r[3]) : "r"(addr));
}
__device__ __forceinline__ void ldsm4t(uint32_t (&r)[4], uint32_t addr) {
    asm volatile("ldmatrix.sync.aligned.m8n8.x4.trans.shared.b16 {%0,%1,%2,%3}, [%4];"
        : "=r"(r[0]), "=r"(r[1]), "=r"(r[2]), "=r"(r[3]) : "r"(addr));
}
__device__ __forceinline__ void mma16816(float (&d)[4], const uint32_t (&a)[4],
                                         uint32_t b0, uint32_t b1) {
    asm volatile(
        "mma.sync.aligned.m16n8k16.row.col.f32.f16.f16.f32 "
        "{%0,%1,%2,%3}, {%4,%5,%6,%7}, {%8,%9}, {%0,%1,%2,%3};"
        : "+f"(d[0]), "+f"(d[1]), "+f"(d[2]), "+f"(d[3])
        : "r"(a[0]), "r"(a[1]), "r"(a[2]), "r"(a[3]), "r"(b0), "r"(b1));
}
__device__ __forceinline__ void cp16(uint32_t dst, const void* src) {
    asm volatile("cp.async.cg.shared.global [%0], [%1], 16;"
                 :: "r"(dst), "l"(src) : "memory");
}
#define CP_COMMIT() asm volatile("cp.async.commit_group;" ::: "memory")
#define CP_WAIT0()  asm volatile("cp.async.wait_group 0;" ::: "memory")

__device__ __forceinline__ ushort_t fp16hi(float v) {
    return __half_as_ushort(__float2half_rn(v));
}

// ---------------------------------------------------------------------------
// merged prep: grid.x sections [0,96) w_attn | [96,128) w_proj | [128,384) x
// grid = (384, 32), 256 threads
// ---------------------------------------------------------------------------
__global__ __launch_bounds__(256) void prep_all_kernel(
    const float* __restrict__ X, const float* __restrict__ WA,
    const float* __restrict__ WP, ushort_t* __restrict__ Xh,
    ushort_t* __restrict__ WAt, ushort_t* __restrict__ WPt)
{
    const int bx = blockIdx.x;
    if (bx >= 128) {
        // x conversion: row = (bx-128)*32 + by, 256 float4 per row
        if (blockIdx.y == 0 || true) {
            const size_t r = (size_t)(bx - 128) * 32 + blockIdx.y;
            const int c4 = threadIdx.x << 2;
            float4 v = *(const float4*)(X + r * 1024 + c4);
            *(ushort4*)(Xh + r * 1024 + c4) =
                make_ushort4(fp16hi(v.x), fp16hi(v.y), fp16hi(v.z), fp16hi(v.w));
        }
        return;
    }
    const bool is_wa = (bx < 96);
    const float* W = is_wa ? WA : WP;
    ushort_t* Wt   = is_wa ? WAt : WPt;
    const int N    = is_wa ? C3_ : C_;
    const int n0   = (is_wa ? bx : (bx - 96)) << 5;
    const int k0   = blockIdx.y << 5;

    __shared__ float t[32][33];
    const int row = threadIdx.x >> 5;
    const int col = threadIdx.x & 31;
    #pragma unroll
    for (int p = 0; p < 4; ++p)
        t[row + p * 8][col] = W[(size_t)(k0 + row + p * 8) * N + n0 + col];
    __syncthreads();
    #pragma unroll
    for (int p = 0; p < 4; ++p) {
        int n = row + p * 8, k = col;
        Wt[(size_t)(n0 + n) * KW_ + k0 + k] = fp16hi(t[k][n]);
    }
}

// ---------------------------------------------------------------------------
// 1-term HMMA GEMM (R14-exact: BK=32, 2-stage cp.async pipeline).
// EPI: 0 -> fp32 C[M][N] ; 2 -> fp16 hi, row stride 3072
// ---------------------------------------------------------------------------
#define PITCH 40
#define ABUF  (128 * PITCH)
#define ROWBLK (16 * PITCH * 2)

template<int EPI>
__global__ __launch_bounds__(256, 2) void gemm_mma_kernel(
    const ushort_t* __restrict__ A, const ushort_t* __restrict__ Bh,
    const float* __restrict__ bias, void* __restrict__ Cout, int N, int n_base,
    int astride)
{
    extern __shared__ ushort_t gs[];
    ushort_t* sAh = gs;
    ushort_t* sBs = gs + 2 * ABUF;

    const int tid  = threadIdx.x;
    const int lane = tid & 31, wid = tid >> 5;
    const int m0 = blockIdx.y << 7;
    const int n0 = n_base + (blockIdx.x << 7);
    const int wm = (wid & 1) << 6;
    const int wn = (wid >> 1) << 5;

    float acc[4][4][4];
    #pragma unroll
    for (int i = 0; i < 4; i++)
        #pragma unroll
        for (int j = 0; j < 4; j++)
            #pragma unroll
            for (int k = 0; k < 4; k++) acc[i][j][k] = 0.0f;

    const int r0s = tid >> 2, r1s = r0s + 64;
    const int js  = (tid & 3) << 3;
    const ushort_t* gA0 = A + (size_t)(m0 + r0s) * astride + js;
    const ushort_t* gA1 = A + (size_t)(m0 + r1s) * astride + js;
    const ushort_t* gB0 = Bh + (size_t)(n0 + r0s) * KW_ + js;
    const ushort_t* gB1 = Bh + (size_t)(n0 + r1s) * KW_ + js;
    const uint32_t so0b = (uint32_t)(r0s * PITCH + js) * 2;
    const uint32_t so1b = (uint32_t)(r1s * PITCH + js) * 2;

    const uint32_t uAh = smem_u32(sAh), uBs = smem_u32(sBs);
    const uint32_t AB2 = ABUF * 2;
    const uint32_t aoff = (uint32_t)((wm + (lane & 15)) * PITCH + (lane >> 4) * 8) * 2;
    const uint32_t boff = (uint32_t)((wn + (lane & 7) + ((lane >> 4) << 3)) * PITCH
                                     + ((lane >> 3) & 1) * 8) * 2;

    cp16(uAh + so0b, gA0); cp16(uAh + so1b, gA1);
    cp16(uBs + so0b, gB0); cp16(uBs + so1b, gB1);
    CP_COMMIT();
    CP_WAIT0();
    __syncthreads();

    for (int c = 0; c < 32; ++c) {
        const int buf = c & 1;
        if (c + 1 < 32) {
            const int kc = (c + 1) << 5;
            const uint32_t nb = (uint32_t)(1 - buf) * AB2;
            cp16(uAh + nb + so0b, gA0 + kc);
            cp16(uAh + nb + so1b, gA1 + kc);
            cp16(uBs + nb + so0b, gB0 + kc);
            cp16(uBs + nb + so1b, gB1 + kc);
            CP_COMMIT();
        }

        const uint32_t aHB = uAh + buf * AB2 + aoff;
        const uint32_t bBB = uBs + buf * AB2 + boff;

        uint32_t af[2][4][4], bf[2][2][4];
        ldsm4(bf[0][0], bBB);
        ldsm4(bf[0][1], bBB + ROWBLK);
        #pragma unroll
        for (int mi = 0; mi < 4; ++mi)
            ldsm4(af[0][mi], aHB + mi * ROWBLK);

        #pragma unroll
        for (int ph = 0; ph < 2; ++ph) {
            if (ph == 0) {
                ldsm4(bf[1][0], bBB + 32);
                ldsm4(bf[1][1], bBB + ROWBLK + 32);
                #pragma unroll
                for (int mi = 0; mi < 4; ++mi)
                    ldsm4(af[1][mi], aHB + mi * ROWBLK + 32);
            }
            #pragma unroll
            for (int mi = 0; mi < 4; ++mi) {
                mma16816(acc[mi][0], af[ph][mi], bf[ph][0][0], bf[ph][0][1]);
                mma16816(acc[mi][1], af[ph][mi], bf[ph][0][2], bf[ph][0][3]);
                mma16816(acc[mi][2], af[ph][mi], bf[ph][1][0], bf[ph][1][1]);
                mma16816(acc[mi][3], af[ph][mi], bf[ph][1][2], bf[ph][1][3]);
            }
        }

        if (c + 1 < 32) CP_WAIT0();
        __syncthreads();
    }

    const int g  = lane >> 2;
    const int tg = (lane & 3) << 1;
    #pragma unroll
    for (int ni = 0; ni < 4; ++ni) {
        int col = n0 + wn + ni * 8 + tg;
        float2 bv = *(const float2*)(bias + col);
        #pragma unroll
        for (int mi = 0; mi < 4; ++mi) {
            int r0 = m0 + wm + mi * 16 + g;
            float a0 = acc[mi][ni][0] + bv.x, a1 = acc[mi][ni][1] + bv.y;
            float a2 = acc[mi][ni][2] + bv.x, a3 = acc[mi][ni][3] + bv.y;
            if (EPI == 0) {
                float* C = (float*)Cout;
                *(float2*)&C[(size_t)r0 * N + col]       = make_float2(a0, a1);
                *(float2*)&C[(size_t)(r0 + 8) * N + col] = make_float2(a2, a3);
            } else {
                ushort_t* C = (ushort_t*)Cout;
                *(ushort2*)&C[(size_t)r0 * C3_ + col] =
                    make_ushort2(fp16hi(a0), fp16hi(a1));
                *(ushort2*)&C[(size_t)(r0 + 8) * C3_ + col] =
                    make_ushort2(fp16hi(a2), fp16hi(a3));
            }
        }
    }
}

// ---------------------------------------------------------------------------
// Fused attention (R16 structure + hoisted Q fragments).
// q-block 32, 256 threads, 2 CTAs/SM; packed half2 epilogues.
// ---------------------------------------------------------------------------
struct SmemAttn6 {
    float l_red[32];
    float l_inv[32];
    ushort_t S[32 * PS_];                                 // 66048 B
    union {
        struct { ushort_t Qh[32 * PQ_]; ushort_t Kh[2][128 * PQ_]; } p1;
        struct { ushort_t Vs[2][128 * PQ_]; } p2;
    } u;
};

__global__ __launch_bounds__(256, 2) void fused_attn_mma_kernel(
    const ushort_t* __restrict__ QKVh, ushort_t* __restrict__ Yh)
{
    extern __shared__ char smem_raw[];
    SmemAttn6& sm = *reinterpret_cast<SmemAttn6*>(smem_raw);

    const int qb = blockIdx.x;       // 0..31
    const int bh = blockIdx.y;       // 0..127
    const int b  = bh >> 4;
    const int h  = bh & 15;
    const int hc = h * HD_;
    const ushort_t* base = QKVh + (size_t)b * T_ * C3_;

    const int tid  = threadIdx.x;
    const int lane = tid & 31, wid = tid >> 5;
    const int q0   = qb << 5;
    const int g    = lane >> 2;

    if (tid < 32) sm.l_red[tid] = 0.0f;

    const uint32_t sQh = smem_u32(sm.u.p1.Qh);
    const uint32_t sK0 = smem_u32(sm.u.p1.Kh[0]);
    const uint32_t sS  = smem_u32(sm.S);
    const uint32_t KBUF = 128 * PQ_ * 2;

    {
        int r = tid >> 3, j = tid & 7;
        cp16(sQh + (uint32_t)(r * PQ_ + (j << 3)) * 2,
             base + (size_t)(q0 + r) * C3_ + hc + (j << 3));
    }
    #pragma unroll
    for (int l = 0; l < 4; ++l) {
        int c = tid + (l << 8);
        int r = c >> 3, j = c & 7;
        cp16(sK0 + (uint32_t)(r * PQ_ + (j << 3)) * 2,
             base + (size_t)r * C3_ + 1024 + hc + (j << 3));
    }
    CP_COMMIT();
    CP_WAIT0();
    __syncthreads();

    const int wm = (wid & 1) << 4;
    const int wn = (wid >> 1) << 5;
    const uint32_t aoff = (uint32_t)((wm + (lane & 15)) * PQ_ + (lane >> 4) * 8) * 2;
    const uint32_t boff = (uint32_t)((wn + (lane & 7) + ((lane >> 4) << 3)) * PQ_
                                     + ((lane >> 3) & 1) * 8) * 2;

    // hoisted Q fragments (loop-invariant across all K tiles)
    uint32_t afq[4][4];
    #pragma unroll
    for (int ks = 0; ks < 4; ++ks)
        ldsm4(afq[ks], sQh + aoff + ks * 32);

    float lsum[2] = {0.0f, 0.0f};

    for (int t = 0; t < 8; ++t) {
        const int k0 = t << 7;
        const int buf = t & 1;
        if (t + 1 < 8) {
            const uint32_t dstK = sK0 + (uint32_t)(1 - buf) * KBUF;
            #pragma unroll
            for (int l = 0; l < 4; ++l) {
                int c = tid + (l << 8);
                int r = c >> 3, j = c & 7;
                cp16(dstK + (uint32_t)(r * PQ_ + (j << 3)) * 2,
                     base + (size_t)(k0 + 128 + r) * C3_ + 1024 + hc + (j << 3));
            }
            CP_COMMIT();
        }

        const uint32_t sKb = sK0 + (uint32_t)buf * KBUF;

        float acc[4][4];
        #pragma unroll
        for (int j = 0; j < 4; ++j)
            #pragma unroll
            for (int k = 0; k < 4; ++k) acc[j][k] = 0.0f;

        #pragma unroll
        for (int ks = 0; ks < 4; ++ks) {
            uint32_t bf[2][4];
            ldsm4(bf[0], sKb + boff + ks * 32);
            ldsm4(bf[1], sKb + boff + (16 * PQ_ * 2) + ks * 32);
            mma16816(acc[0], afq[ks], bf[0][0], bf[0][1]);
            mma16816(acc[1], afq[ks], bf[0][2], bf[0][3]);
            mma16816(acc[2], afq[ks], bf[1][0], bf[1][1]);
            mma16816(acc[3], afq[ks], bf[1][2], bf[1][3]);
        }

        // exp epilogue -> smem S panel (packed cvt), fp32 row sums
        #pragma unroll
        for (int ni = 0; ni < 4; ++ni) {
            float e0 = __expf(acc[ni][0] * 0.125f);
            float e1 = __expf(acc[ni][1] * 0.125f);
            float e2 = __expf(acc[ni][2] * 0.125f);
            float e3 = __expf(acc[ni][3] * 0.125f);
            lsum[0] += e0 + e1;
            lsum[1] += e2 + e3;
            int col = k0 + wn + ni * 8 + ((lane & 3) << 1);
            int r0  = wm + g;
            *(__half2*)&sm.S[(size_t)r0 * PS_ + col]       = __floats2half2_rn(e0, e1);
            *(__half2*)&sm.S[(size_t)(r0 + 8) * PS_ + col] = __floats2half2_rn(e2, e3);
        }

        if (t + 1 < 8) CP_WAIT0();
        __syncthreads();
    }

    #pragma unroll
    for (int i = 0; i < 2; i++) {
        float v = lsum[i];
        v += __shfl_xor_sync(0xFFFFFFFFu, v, 1);
        v += __shfl_xor_sync(0xFFFFFFFFu, v, 2);
        if ((lane & 3) == 0)
            atomicAdd(&sm.l_red[wm + g + i * 8], v);
    }
    __syncthreads();
    if (tid < 32) sm.l_inv[tid] = 1.0f / sm.l_red[tid];
    __syncthreads();

    const uint32_t sV0 = smem_u32(sm.u.p2.Vs[0]);
    #pragma unroll
    for (int l = 0; l < 4; ++l) {
        int c = tid + (l << 8);
        int r = c >> 3, j = c & 7;
        cp16(sV0 + (uint32_t)(r * PQ_ + (j << 3)) * 2,
             base + (size_t)r * C3_ + 2048 + hc + (j << 3));
    }
    CP_COMMIT();

    // in-place transform: P = relu(e * linv - TH), packed half2
    {
        const __half2 th2 = __float2half2_rn(TH_);
        const __half2 z2  = __float2half2_rn(0.0f);
        #pragma unroll
        for (int l = 0; l < 16; ++l) {
            int idx = tid + (l << 8);
            int r   = idx >> 7;
            int c8  = (idx & 127) << 3;
            __half2* p = (__half2*)&sm.S[(size_t)r * PS_ + c8];
            const __half2 iv2 = __float2half2_rn(sm.l_inv[r]);
            __half2 v0 = p[0], v1 = p[1], v2 = p[2], v3 = p[3];
            v0 = __hmax2(__hsub2(__hmul2(v0, iv2), th2), z2);
            v1 = __hmax2(__hsub2(__hmul2(v1, iv2), th2), z2);
            v2 = __hmax2(__hsub2(__hmul2(v2, iv2), th2), z2);
            v3 = __hmax2(__hsub2(__hmul2(v3, iv2), th2), z2);
            p[0] = v0; p[1] = v1; p[2] = v2; p[3] = v3;
        }
    }
    CP_WAIT0();
    __syncthreads();

    const int wm2 = (wid & 1) << 4;
    const int wn2 = (wid >> 1) << 4;
    const uint32_t aoff2 = (uint32_t)((wm2 + (lane & 15)) * PS_ + (lane >> 4) * 8) * 2;
    const uint32_t boff2t = (uint32_t)((lane & 15) * PQ_ + wn2 + ((lane >> 4) << 3)) * 2;

    float accy[2][4];
    #pragma unroll
    for (int j = 0; j < 2; ++j)
        #pragma unroll
        for (int k = 0; k < 4; ++k) accy[j][k] = 0.0f;

    for (int t = 0; t < 8; ++t) {
        const int kc = t << 7;
        const int buf = t & 1;
        if (t + 1 < 8) {
            const uint32_t dstV = sV0 + (uint32_t)(1 - buf) * KBUF;
            #pragma unroll
            for (int l = 0; l < 4; ++l) {
                int c = tid + (l << 8);
                int r = c >> 3, j = c & 7;
                cp16(dstV + (uint32_t)(r * PQ_ + (j << 3)) * 2,
                     base + (size_t)(kc + 128 + r) * C3_ + 2048 + hc + (j << 3));
            }
            CP_COMMIT();
        }

        const uint32_t sVb = sV0 + (uint32_t)buf * KBUF;

        #pragma unroll
        for (int ks = 0; ks < 8; ++ks) {
            uint32_t bf[4];
            ldsm4t(bf, sVb + boff2t + ks * (16 * PQ_ * 2));
            uint32_t af[4];
            ldsm4(af, sS + aoff2 + (uint32_t)kc * 2 + ks * 32);
            mma16816(accy[0], af, bf[0], bf[1]);
            mma16816(accy[1], af, bf[2], bf[3]);
        }

        if (t + 1 < 8) CP_WAIT0();
        __syncthreads();
    }

    #pragma unroll
    for (int ni = 0; ni < 2; ++ni) {
        int ch = hc + wn2 + ni * 8 + ((lane & 3) << 1);
        #pragma unroll
        for (int hv = 0; hv < 2; ++hv) {
            int rq = q0 + wm2 + g + hv * 8;
            size_t rg = ((size_t)b * T_ + rq) * C_;
            *(__half2*)&Yh[rg + ch] =
                __floats2half2_rn(accy[ni][hv * 2 + 0], accy[ni][hv * 2 + 1]);
        }
    }
}

// ---------------------------------------------------------------------------
extern "C" void kernel_launch(void* const* d_in, const int* in_sizes, int n_in,
                              void* d_out, int out_size)
{
    const float* x      = (const float*)d_in[0];
    const float* w_attn = (const float*)d_in[1];
    const float* b_attn = (const float*)d_in[2];
    const float* w_proj = (const float*)d_in[3];
    const float* b_proj = (const float*)d_in[4];
    float* out = (float*)d_out;

    ushort_t *qkvh, *yh, *xh, *wa, *wp;
    cudaGetSymbolAddress((void**)&qkvh, g_qkvh);
    cudaGetSymbolAddress((void**)&yh,   g_yh);
    cudaGetSymbolAddress((void**)&xh,   g_xh);
    cudaGetSymbolAddress((void**)&wa,   g_wa);
    cudaGetSymbolAddress((void**)&wp,   g_wp);

    const int gsmem = 4 * ABUF * 2;   // 40960 B (2-stage A + B)
    cudaFuncSetAttribute(gemm_mma_kernel<2>,
                         cudaFuncAttributeMaxDynamicSharedMemorySize, gsmem);
    cudaFuncSetAttribute(gemm_mma_kernel<0>,
                         cudaFuncAttributeMaxDynamicSharedMemorySize, gsmem);
    cudaFuncSetAttribute(fused_attn_mma_kernel,
                         cudaFuncAttributeMaxDynamicSharedMemorySize,
                         (int)sizeof(SmemAttn6));

    // merged prep (weights + x)
    prep_all_kernel<<<dim3(384, 32), 256>>>(x, w_attn, w_proj, xh, wa, wp);

    // 1) QKV projection (1-term, fp16-hi out)
    gemm_mma_kernel<2><<<dim3(24, 64), 256, gsmem>>>(
        xh, wa, b_attn, qkvh, C3_, 0, C_);

    // 2) fused attention
    fused_attn_mma_kernel<<<dim3(32, 128), 256, sizeof(SmemAttn6)>>>(qkvh, yh);

    // 3) output projection (fp32 out)
    gemm_mma_kernel<0><<<dim3(8, 64), 256, gsmem>>>(
        yh, wp, b_proj, out, C_, 0, C_);
}